// round 16
// baseline (speedup 1.0000x reference)
#include <cuda_runtime.h>
#include <cstdint>

#define BB 64
#define CH 128
#define HH 40
#define WW 96
#define NELEM (BB*CH*HH*WW)          // 31,457,280
#define WTOT  (4*5*9*128*128)        // 2,949,120

// Scratch: transposed weights [dir][iter][k][ci][co] and ping-pong y buffers.
__device__ float g_wt[WTOT];
__device__ float g_buf[2][NELEM];

#define FFMA2(acc, a, b) asm("fma.rn.f32x2 %0, %1, %2, %0;" : "+l"(acc) : "l"(a), "l"(b))
#define SPLAT(d, f)      asm("mov.b64 %0, {%1, %1};" : "=l"(d) : "r"(__float_as_uint(f)))

__device__ __forceinline__ uint32_t smem_u32(const void* p) {
    return (uint32_t)__cvta_generic_to_shared(p);
}
__device__ __forceinline__ void cpa16(uint32_t s, const void* g) {
    asm volatile("cp.async.ca.shared.global [%0], [%1], 16;" :: "r"(s), "l"(g));
}
#define CP_COMMIT() asm volatile("cp.async.commit_group;" ::: "memory")
#define CP_WAIT0()  asm volatile("cp.async.wait_group 0;" ::: "memory")

// Injective weight swizzle at float4 granularity: block g (8 float4s) shifts by g.
// write: d4 = c4 + (c4>>3); read base for co-group g: woff = 8*g + 4*(g>>2).
// Worst-case 2-way bank conflict on the 16-lane weight read.
__device__ __forceinline__ int wswz(int c4) { return c4 + (c4 >> 3); }

// ---------------------------------------------------------------------------
// One-time weight transpose: w[((it*128+co)*128+ci)*9+k] -> g_wt[(((d*5+it)*9+k)*128+ci)*128+co]
// ---------------------------------------------------------------------------
__global__ void transpose_w_kernel(const float* __restrict__ wd, const float* __restrict__ wu,
                                   const float* __restrict__ wr, const float* __restrict__ wl) {
    int tid = blockIdx.x * 256 + threadIdx.x;
    if (tid >= WTOT) return;
    int co = tid & 127;
    int ci = (tid >> 7) & 127;
    int q  = tid >> 14;          // (d*5+it)*9 + k
    int k  = q % 9;
    int r  = q / 9;              // d*5 + it
    int it = r % 5;
    int d  = r / 5;
    const float* w = (d == 0) ? wd : (d == 1) ? wu : (d == 2) ? wr : wl;
    g_wt[tid] = w[((size_t)(it * 128 + co) * 128 + ci) * 9 + k];
}

// Weight chunk stage (ci-chunk = 4): rows rest = k*4+cil (36), c4 = 0..31.
// global ci base = chunk*4.
#define WSHB_ROWF 140
#define WSHB_F    (36*WSHB_ROWF)                // 5,040 floats per buffer

template<int NTHR>
__device__ __forceinline__ void stage_wchunk(float* wb, const float* w9, int ci0, int t) {
#pragma unroll
    for (int i = t; i < 1152; i += NTHR) {
        int c4 = i & 31, rest = i >> 5;          // rest = k*4 + cil
        cpa16(smem_u32(&wb[rest * WSHB_ROWF + wswz(c4) * 4]),
              w9 + ((size_t)((rest >> 2) * 128 + ci0 + (rest & 3))) * 128 + c4 * 4);
    }
}

// ---------------------------------------------------------------------------
// Horizontal conv step (1x9 along W, roll along H): phases D and U.
// CTA per (b, h). 192 threads: tx(16)=8 co, ty(12)=8 w. 32 ci-chunks of 4,
// cp.async double-buffered weight staging (1 barrier/chunk, latency hidden).
// Input splats bb[16] reused across 9 taps. Epilogue staged via smem RMW.
// ---------------------------------------------------------------------------
#define INP_H_F   (128*104)                     // 13,312 floats
#define SMEM_H    ((INP_H_F + 2*WSHB_F)*4)      // 93,568 bytes

__global__ __launch_bounds__(192, 2)
void step_h_kernel(const float* __restrict__ src_ext, float* __restrict__ dst_ext,
                   int src_sel, int dst_sel, int widx, int hshift) {
    const float* src = (src_sel >= 0) ? g_buf[src_sel] : src_ext;
    float*       dst = (dst_sel >= 0) ? g_buf[dst_sel] : dst_ext;
    const float* w9  = g_wt + (size_t)widx * 9 * 128 * 128;

    extern __shared__ float sm[];
    float* inP = sm;                 // [128][104], tap index p = w + 4
    float* Wb0 = sm + INP_H_F;       // double-buffered weights [36][140]
    float* Wb1 = Wb0 + WSHB_F;

    int b = blockIdx.y, h = blockIdx.x;
    int t = threadIdx.x;
    int hs = h + hshift; if (hs >= HH) hs -= HH;

    // Async load rolled input row y[b, ci, hs, :] for all 128 ci.
    const float* srow = src + ((size_t)b * CH * HH + hs) * WW;
#pragma unroll
    for (int i = t; i < 128 * 24; i += 192) {
        int ci = i / 24, wv = i % 24;
        cpa16(smem_u32(&inP[ci * 104 + 4 + wv * 4]), srow + (size_t)ci * HH * WW + wv * 4);
    }
    {   // zero pads p 0..3 and 100..103 on every ci row
        float4 z4 = make_float4(0.f, 0.f, 0.f, 0.f);
        for (int i = t; i < 256; i += 192) {
            int ci = i >> 1, side = i & 1;
            *(float4*)&inP[ci * 104 + side * 100] = z4;
        }
    }
    stage_wchunk<192>(Wb0, w9, 0, t);
    CP_COMMIT();

    int tx = t & 15, ty = t >> 4;          // tx: co group, ty: w group
    int co0 = tx * 8, w0 = ty * 8;
    int woff = 8 * tx + 4 * (tx >> 2);     // swizzled smem float offset of co0

    unsigned long long acc[4][8];
#pragma unroll
    for (int j = 0; j < 4; ++j)
#pragma unroll
        for (int jj = 0; jj < 8; ++jj) acc[j][jj] = 0ull;

#pragma unroll 1
    for (int ch = 0; ch < 32; ++ch) {      // 4 ci per chunk
        CP_WAIT0();
        __syncthreads();                   // chunk ch staged + prior reads done
        if (ch < 31) {
            stage_wchunk<192>((ch & 1) ? Wb0 : Wb1, w9, (ch + 1) * 4, t);
            CP_COMMIT();
        }
        const float* buf = (ch & 1) ? Wb1 : Wb0;

#pragma unroll 1
        for (int cil = 0; cil < 4; ++cil) {
            const float* ib = inP + (ch * 4 + cil) * 104 + w0;
            float4 q0 = *(const float4*)(ib);
            float4 q1 = *(const float4*)(ib + 4);
            float4 q2 = *(const float4*)(ib + 8);
            float4 q3 = *(const float4*)(ib + 12);
            unsigned long long bb[16];
            SPLAT(bb[0], q0.x);  SPLAT(bb[1], q0.y);  SPLAT(bb[2], q0.z);  SPLAT(bb[3], q0.w);
            SPLAT(bb[4], q1.x);  SPLAT(bb[5], q1.y);  SPLAT(bb[6], q1.z);  SPLAT(bb[7], q1.w);
            SPLAT(bb[8], q2.x);  SPLAT(bb[9], q2.y);  SPLAT(bb[10], q2.z); SPLAT(bb[11], q2.w);
            SPLAT(bb[12], q3.x); SPLAT(bb[13], q3.y); SPLAT(bb[14], q3.z); SPLAT(bb[15], q3.w);

            const float* wrow = buf + cil * WSHB_ROWF + woff;
#pragma unroll
            for (int k = 0; k < 9; ++k) {
                ulonglong2 a01 = *(const ulonglong2*)(wrow + k * 4 * WSHB_ROWF);
                ulonglong2 a23 = *(const ulonglong2*)(wrow + k * 4 * WSHB_ROWF + 4);
#pragma unroll
                for (int jj = 0; jj < 8; ++jj) {
                    FFMA2(acc[0][jj], a01.x, bb[k + jj]);
                    FFMA2(acc[1][jj], a01.y, bb[k + jj]);
                    FFMA2(acc[2][jj], a23.x, bb[k + jj]);
                    FFMA2(acc[3][jj], a23.y, bb[k + jj]);
                }
            }
        }
    }

    // Stage 2*relu(conv) into smem [w][co] (stride 130), then coalesced RMW.
    __syncthreads();
    float* so = inP;                       // reuse: needs 96*130 = 12,480 floats
#pragma unroll
    for (int j = 0; j < 4; ++j) {
#pragma unroll
        for (int jj = 0; jj < 8; ++jj) {
            unsigned int lo, hi;
            asm("mov.b64 {%0, %1}, %2;" : "=r"(lo), "=r"(hi) : "l"(acc[j][jj]));
            float v0 = 2.0f * fmaxf(__uint_as_float(lo), 0.f);
            float v1 = 2.0f * fmaxf(__uint_as_float(hi), 0.f);
            *(float2*)&so[(w0 + jj) * 130 + co0 + 2 * j] = make_float2(v0, v1);
        }
    }
    __syncthreads();
    for (int i = t; i < 128 * 96; i += 192) {
        int w = i % 96, co = i / 96;
        size_t gi = (((size_t)b * CH + co) * HH + h) * WW + w;
        dst[gi] = src[gi] + so[w * 130 + co];
    }
}

// ---------------------------------------------------------------------------
// Vertical conv step (9x1 along H, roll along W): phases R and L.
// CTA per (b, 4-wide w tile). 256 threads: co_g(16)=8 co, h_g(8)=5 h, w_g(2)=w pair.
// 32 ci-chunks of 4 (ci halves in inP), cp.async double-buffered weights.
// f32x2 lanes = adjacent w pair (LDS.64 input), weight splats reused across 5 h.
// ---------------------------------------------------------------------------
#define INP_V_F   (64*48*4)                 // 12,288 floats
#define SMEM_V    ((INP_V_F + 2*WSHB_F)*4)  // 89,472 bytes

__global__ __launch_bounds__(256, 2)
void step_v_kernel(const float* __restrict__ src_ext, float* __restrict__ dst_ext,
                   int src_sel, int dst_sel, int widx, int wshift) {
    const float* src = (src_sel >= 0) ? g_buf[src_sel] : src_ext;
    float*       dst = (dst_sel >= 0) ? g_buf[dst_sel] : dst_ext;
    const float* w9  = g_wt + (size_t)widx * 9 * 128 * 128;

    extern __shared__ float sm[];
    float* inP = sm;                 // [64][48][4]  (h padded by 4 each side)
    float* Wb0 = sm + INP_V_F;
    float* Wb1 = Wb0 + WSHB_F;

    int b  = blockIdx.y;
    int w0 = blockIdx.x * 4;
    int t  = threadIdx.x;
    int co_g = t & 15, h_g = (t >> 4) & 7, w_g = t >> 7;   // 16 x 8 x 2
    int co0 = co_g * 8, h0 = h_g * 5;
    int woff = 8 * co_g + 4 * (co_g >> 2);

    int ws[4];
#pragma unroll
    for (int wl = 0; wl < 4; ++wl) {
        int v = w0 + wl + wshift;
        ws[wl] = (v >= WW) ? v - WW : v;
    }

    // Zero pads once (h rows 0..3 and 44..47 stay zero across the cc reload).
    for (int i = t; i < 64 * 8 * 4; i += 256) {
        int wl  = i & 3;
        int r   = (i >> 2) & 7;
        int cil = i >> 5;
        int hp  = (r < 4) ? r : (r + 40);
        inP[(cil * 48 + hp) * 4 + wl] = 0.f;
    }
    // Load ci half 0 (rolled columns).
    {
        const float* sb = src + (size_t)b * CH * HH * WW;
        for (int i = t; i < 64 * 40 * 4; i += 256) {
            int wl  = i & 3;
            int hh  = (i >> 2) % 40;
            int cil = i / 160;
            inP[(cil * 48 + 4 + hh) * 4 + wl] = sb[((size_t)cil * HH + hh) * WW + ws[wl]];
        }
    }
    stage_wchunk<256>(Wb0, w9, 0, t);
    CP_COMMIT();

    unsigned long long acc[8][5];
#pragma unroll
    for (int c = 0; c < 8; ++c)
#pragma unroll
        for (int jj = 0; jj < 5; ++jj) acc[c][jj] = 0ull;

#pragma unroll 1
    for (int q = 0; q < 32; ++q) {         // global ci base = q*4
        CP_WAIT0();
        __syncthreads();
        if (q == 16) {                     // switch inP to ci half 1
            const float* sb = src + ((size_t)b * CH + 64) * HH * WW;
            for (int i = t; i < 64 * 40 * 4; i += 256) {
                int wl  = i & 3;
                int hh  = (i >> 2) % 40;
                int cil = i / 160;
                inP[(cil * 48 + 4 + hh) * 4 + wl] = sb[((size_t)cil * HH + hh) * WW + ws[wl]];
            }
        }
        if (q < 31) {
            stage_wchunk<256>((q & 1) ? Wb0 : Wb1, w9, (q + 1) * 4, t);
            CP_COMMIT();
        }
        if (q == 16) __syncthreads();      // new inP visible before compute
        const float* buf = (q & 1) ? Wb1 : Wb0;

#pragma unroll 1
        for (int cil = 0; cil < 4; ++cil) {
            const float* wrow = buf + cil * WSHB_ROWF + woff;
            const float* irow = inP + ((((q & 15) * 4) + cil) * 48 + h0) * 4 + w_g * 2;
#pragma unroll
            for (int k = 0; k < 9; ++k) {
                float4 wa = *(const float4*)(wrow + k * 4 * WSHB_ROWF);
                float4 wb = *(const float4*)(wrow + k * 4 * WSHB_ROWF + 4);
                unsigned long long ip[5];
#pragma unroll
                for (int jj = 0; jj < 5; ++jj)
                    ip[jj] = *(const unsigned long long*)(irow + (k + jj) * 4);
                unsigned long long s0, s1, s2, s3, s4, s5, s6, s7;
                SPLAT(s0, wa.x); SPLAT(s1, wa.y); SPLAT(s2, wa.z); SPLAT(s3, wa.w);
                SPLAT(s4, wb.x); SPLAT(s5, wb.y); SPLAT(s6, wb.z); SPLAT(s7, wb.w);
#pragma unroll
                for (int jj = 0; jj < 5; ++jj) {
                    FFMA2(acc[0][jj], s0, ip[jj]);
                    FFMA2(acc[1][jj], s1, ip[jj]);
                    FFMA2(acc[2][jj], s2, ip[jj]);
                    FFMA2(acc[3][jj], s3, ip[jj]);
                    FFMA2(acc[4][jj], s4, ip[jj]);
                    FFMA2(acc[5][jj], s5, ip[jj]);
                    FFMA2(acc[6][jj], s6, ip[jj]);
                    FFMA2(acc[7][jj], s7, ip[jj]);
                }
            }
        }
    }

    // Stage 2*relu(conv) into smem [h][co][4w], then float4 global RMW.
    __syncthreads();
    float* so = sm;                    // needs 40*128*4 = 20,480 <= 22,368 floats
#pragma unroll
    for (int c = 0; c < 8; ++c) {
#pragma unroll
        for (int jj = 0; jj < 5; ++jj) {
            unsigned int lo, hi;
            asm("mov.b64 {%0, %1}, %2;" : "=r"(lo), "=r"(hi) : "l"(acc[c][jj]));
            float v0 = 2.0f * fmaxf(__uint_as_float(lo), 0.f);
            float v1 = 2.0f * fmaxf(__uint_as_float(hi), 0.f);
            *(float2*)&so[((h0 + jj) * 128 + co0 + c) * 4 + w_g * 2] = make_float2(v0, v1);
        }
    }
    __syncthreads();
    for (int i = t; i < 40 * 128; i += 256) {
        int hh = i >> 7, co = i & 127;
        float4 sv = *(const float4*)&so[i * 4];
        size_t gi = (((size_t)b * CH + co) * HH + hh) * WW + w0;
        float4 s4 = *(const float4*)(src + gi);
        float4 o4;
        o4.x = s4.x + sv.x; o4.y = s4.y + sv.y; o4.z = s4.z + sv.z; o4.w = s4.w + sv.w;
        *(float4*)(dst + gi) = o4;
    }
}

// ---------------------------------------------------------------------------
// Launcher: weight transpose + 20 chained step kernels, ping-pong buffers.
// Graph-capturable: kernel launches only.
// ---------------------------------------------------------------------------
extern "C" void kernel_launch(void* const* d_in, const int* in_sizes, int n_in,
                              void* d_out, int out_size) {
    const float* x  = (const float*)d_in[0];
    const float* wd = (const float*)d_in[1];
    const float* wu = (const float*)d_in[2];
    const float* wr = (const float*)d_in[3];
    const float* wl = (const float*)d_in[4];
    float* out = (float*)d_out;

    cudaFuncSetAttribute(step_h_kernel, cudaFuncAttributeMaxDynamicSharedMemorySize, SMEM_H);
    cudaFuncSetAttribute(step_v_kernel, cudaFuncAttributeMaxDynamicSharedMemorySize, SMEM_V);

    transpose_w_kernel<<<(WTOT + 255) / 256, 256>>>(wd, wu, wr, wl);

    static const int offH[5] = {1, 2, 5, 10, 20};    // 40 >> (5-i)
    static const int offW[5] = {3, 6, 12, 24, 48};   // 96 >> (5-i)

    int cur_sel = -1;   // step 0 reads external x
    for (int s = 0; s < 20; ++s) {
        int dst_sel = (s == 19) ? -1 : (s & 1);      // final step writes d_out
        int dir = s / 5, it = s % 5;
        int widx = dir * 5 + it;
        if (dir < 2) {
            int shift = (dir == 0) ? offH[it] : HH - offH[it];
            step_h_kernel<<<dim3(HH, BB), 192, SMEM_H>>>(x, out, cur_sel, dst_sel, widx, shift);
        } else {
            int shift = (dir == 2) ? offW[it] : WW - offW[it];
            step_v_kernel<<<dim3(WW / 4, BB), 256, SMEM_V>>>(x, out, cur_sel, dst_sel, widx, shift);
        }
        cur_sel = dst_sel;
    }
}

// round 17
// speedup vs baseline: 1.0009x; 1.0009x over previous
#include <cuda_runtime.h>
#include <cstdint>

#define BB 64
#define CH 128
#define HH 40
#define WW 96
#define NELEM (BB*CH*HH*WW)          // 31,457,280
#define WTOT  (4*5*9*128*128)        // 2,949,120

// Scratch: transposed weights [dir][iter][k][ci][co] and ping-pong y buffers.
__device__ float g_wt[WTOT];
__device__ float g_buf[2][NELEM];

#define FFMA2(acc, a, b) asm("fma.rn.f32x2 %0, %1, %2, %0;" : "+l"(acc) : "l"(a), "l"(b))
#define SPLAT(d, f)      asm("mov.b64 %0, {%1, %1};" : "=l"(d) : "r"(__float_as_uint(f)))

__device__ __forceinline__ uint32_t smem_u32(const void* p) {
    return (uint32_t)__cvta_generic_to_shared(p);
}
__device__ __forceinline__ void cpa16(uint32_t s, const void* g) {
    asm volatile("cp.async.ca.shared.global [%0], [%1], 16;" :: "r"(s), "l"(g));
}
#define CP_COMMIT() asm volatile("cp.async.commit_group;" ::: "memory")
#define CP_WAIT0()  asm volatile("cp.async.wait_group 0;" ::: "memory")

// Injective weight swizzle at float4 granularity: block g (8 float4s) shifts by g.
// write: d4 = c4 + (c4>>3); read base for co-group g: woff = 8*g + 4*(g>>2).
// Worst-case 2-way bank conflict on the 16-lane weight read.
__device__ __forceinline__ int wswz(int c4) { return c4 + (c4 >> 3); }

// ---------------------------------------------------------------------------
// One-time weight transpose: w[((it*128+co)*128+ci)*9+k] -> g_wt[(((d*5+it)*9+k)*128+ci)*128+co]
// ---------------------------------------------------------------------------
__global__ void transpose_w_kernel(const float* __restrict__ wd, const float* __restrict__ wu,
                                   const float* __restrict__ wr, const float* __restrict__ wl) {
    int tid = blockIdx.x * 256 + threadIdx.x;
    if (tid >= WTOT) return;
    int co = tid & 127;
    int ci = (tid >> 7) & 127;
    int q  = tid >> 14;          // (d*5+it)*9 + k
    int k  = q % 9;
    int r  = q / 9;              // d*5 + it
    int it = r % 5;
    int d  = r / 5;
    const float* w = (d == 0) ? wd : (d == 1) ? wu : (d == 2) ? wr : wl;
    g_wt[tid] = w[((size_t)(it * 128 + co) * 128 + ci) * 9 + k];
}

// Weight chunk stage (ci-chunk = 4): rows rest = k*4+cil (36), c4 = 0..31.
// global ci base = chunk*4.
#define WSHB_ROWF 140
#define WSHB_F    (36*WSHB_ROWF)                // 5,040 floats per buffer

template<int NTHR>
__device__ __forceinline__ void stage_wchunk(float* wb, const float* w9, int ci0, int t) {
#pragma unroll
    for (int i = t; i < 1152; i += NTHR) {
        int c4 = i & 31, rest = i >> 5;          // rest = k*4 + cil
        cpa16(smem_u32(&wb[rest * WSHB_ROWF + wswz(c4) * 4]),
              w9 + ((size_t)((rest >> 2) * 128 + ci0 + (rest & 3))) * 128 + c4 * 4);
    }
}

// ---------------------------------------------------------------------------
// Horizontal conv step (1x9 along W, roll along H): phases D and U.
// CTA per (b, h). 192 threads: tx(16)=8 co, ty(12)=8 w. 32 ci-chunks of 4,
// cp.async double-buffered weight staging (1 barrier/chunk, latency hidden).
// Input splats bb[16] reused across 9 taps. Epilogue staged via smem RMW.
// ---------------------------------------------------------------------------
#define INP_H_F   (128*104)                     // 13,312 floats
#define SMEM_H    ((INP_H_F + 2*WSHB_F)*4)      // 93,568 bytes

__global__ __launch_bounds__(192, 2)
void step_h_kernel(const float* __restrict__ src_ext, float* __restrict__ dst_ext,
                   int src_sel, int dst_sel, int widx, int hshift) {
    const float* src = (src_sel >= 0) ? g_buf[src_sel] : src_ext;
    float*       dst = (dst_sel >= 0) ? g_buf[dst_sel] : dst_ext;
    const float* w9  = g_wt + (size_t)widx * 9 * 128 * 128;

    extern __shared__ float sm[];
    float* inP = sm;                 // [128][104], tap index p = w + 4
    float* Wb0 = sm + INP_H_F;       // double-buffered weights [36][140]
    float* Wb1 = Wb0 + WSHB_F;

    int b = blockIdx.y, h = blockIdx.x;
    int t = threadIdx.x;
    int hs = h + hshift; if (hs >= HH) hs -= HH;

    // Async load rolled input row y[b, ci, hs, :] for all 128 ci.
    const float* srow = src + ((size_t)b * CH * HH + hs) * WW;
#pragma unroll
    for (int i = t; i < 128 * 24; i += 192) {
        int ci = i / 24, wv = i % 24;
        cpa16(smem_u32(&inP[ci * 104 + 4 + wv * 4]), srow + (size_t)ci * HH * WW + wv * 4);
    }
    {   // zero pads p 0..3 and 100..103 on every ci row
        float4 z4 = make_float4(0.f, 0.f, 0.f, 0.f);
        for (int i = t; i < 256; i += 192) {
            int ci = i >> 1, side = i & 1;
            *(float4*)&inP[ci * 104 + side * 100] = z4;
        }
    }
    stage_wchunk<192>(Wb0, w9, 0, t);
    CP_COMMIT();

    int tx = t & 15, ty = t >> 4;          // tx: co group, ty: w group
    int co0 = tx * 8, w0 = ty * 8;
    int woff = 8 * tx + 4 * (tx >> 2);     // swizzled smem float offset of co0

    unsigned long long acc[4][8];
#pragma unroll
    for (int j = 0; j < 4; ++j)
#pragma unroll
        for (int jj = 0; jj < 8; ++jj) acc[j][jj] = 0ull;

#pragma unroll 1
    for (int ch = 0; ch < 32; ++ch) {      // 4 ci per chunk
        CP_WAIT0();
        __syncthreads();                   // chunk ch staged + prior reads done
        if (ch < 31) {
            stage_wchunk<192>((ch & 1) ? Wb0 : Wb1, w9, (ch + 1) * 4, t);
            CP_COMMIT();
        }
        const float* buf = (ch & 1) ? Wb1 : Wb0;

#pragma unroll 1
        for (int cil = 0; cil < 4; ++cil) {
            const float* ib = inP + (ch * 4 + cil) * 104 + w0;
            float4 q0 = *(const float4*)(ib);
            float4 q1 = *(const float4*)(ib + 4);
            float4 q2 = *(const float4*)(ib + 8);
            float4 q3 = *(const float4*)(ib + 12);
            unsigned long long bb[16];
            SPLAT(bb[0], q0.x);  SPLAT(bb[1], q0.y);  SPLAT(bb[2], q0.z);  SPLAT(bb[3], q0.w);
            SPLAT(bb[4], q1.x);  SPLAT(bb[5], q1.y);  SPLAT(bb[6], q1.z);  SPLAT(bb[7], q1.w);
            SPLAT(bb[8], q2.x);  SPLAT(bb[9], q2.y);  SPLAT(bb[10], q2.z); SPLAT(bb[11], q2.w);
            SPLAT(bb[12], q3.x); SPLAT(bb[13], q3.y); SPLAT(bb[14], q3.z); SPLAT(bb[15], q3.w);

            const float* wrow = buf + cil * WSHB_ROWF + woff;
#pragma unroll
            for (int k = 0; k < 9; ++k) {
                ulonglong2 a01 = *(const ulonglong2*)(wrow + k * 4 * WSHB_ROWF);
                ulonglong2 a23 = *(const ulonglong2*)(wrow + k * 4 * WSHB_ROWF + 4);
#pragma unroll
                for (int jj = 0; jj < 8; ++jj) {
                    FFMA2(acc[0][jj], a01.x, bb[k + jj]);
                    FFMA2(acc[1][jj], a01.y, bb[k + jj]);
                    FFMA2(acc[2][jj], a23.x, bb[k + jj]);
                    FFMA2(acc[3][jj], a23.y, bb[k + jj]);
                }
            }
        }
    }

    // Stage 2*relu(conv) into smem [w][co] (stride 130), then coalesced RMW.
    __syncthreads();
    float* so = inP;                       // reuse: needs 96*130 = 12,480 floats
#pragma unroll
    for (int j = 0; j < 4; ++j) {
#pragma unroll
        for (int jj = 0; jj < 8; ++jj) {
            unsigned int lo, hi;
            asm("mov.b64 {%0, %1}, %2;" : "=r"(lo), "=r"(hi) : "l"(acc[j][jj]));
            float v0 = 2.0f * fmaxf(__uint_as_float(lo), 0.f);
            float v1 = 2.0f * fmaxf(__uint_as_float(hi), 0.f);
            *(float2*)&so[(w0 + jj) * 130 + co0 + 2 * j] = make_float2(v0, v1);
        }
    }
    __syncthreads();
    for (int i = t; i < 128 * 96; i += 192) {
        int w = i % 96, co = i / 96;
        size_t gi = (((size_t)b * CH + co) * HH + h) * WW + w;
        dst[gi] = src[gi] + so[w * 130 + co];
    }
}

// ---------------------------------------------------------------------------
// Vertical conv step (9x1 along H, roll along W): phases R and L.
// CTA per (b, 4-wide w tile). 256 threads: co_g(16)=8 co, h_g(8)=5 h, w_g(2)=w pair.
// 32 ci-chunks of 4 (ci halves in inP), cp.async double-buffered weights.
// f32x2 lanes = adjacent w pair (LDS.64 input), weight splats reused across 5 h.
// ---------------------------------------------------------------------------
#define INP_V_F   (64*48*4)                 // 12,288 floats
#define SMEM_V    ((INP_V_F + 2*WSHB_F)*4)  // 89,472 bytes

__global__ __launch_bounds__(256, 2)
void step_v_kernel(const float* __restrict__ src_ext, float* __restrict__ dst_ext,
                   int src_sel, int dst_sel, int widx, int wshift) {
    const float* src = (src_sel >= 0) ? g_buf[src_sel] : src_ext;
    float*       dst = (dst_sel >= 0) ? g_buf[dst_sel] : dst_ext;
    const float* w9  = g_wt + (size_t)widx * 9 * 128 * 128;

    extern __shared__ float sm[];
    float* inP = sm;                 // [64][48][4]  (h padded by 4 each side)
    float* Wb0 = sm + INP_V_F;
    float* Wb1 = Wb0 + WSHB_F;

    int b  = blockIdx.y;
    int w0 = blockIdx.x * 4;
    int t  = threadIdx.x;
    int co_g = t & 15, h_g = (t >> 4) & 7, w_g = t >> 7;   // 16 x 8 x 2
    int co0 = co_g * 8, h0 = h_g * 5;
    int woff = 8 * co_g + 4 * (co_g >> 2);

    int ws[4];
#pragma unroll
    for (int wl = 0; wl < 4; ++wl) {
        int v = w0 + wl + wshift;
        ws[wl] = (v >= WW) ? v - WW : v;
    }

    // Zero pads once (h rows 0..3 and 44..47 stay zero across the cc reload).
    for (int i = t; i < 64 * 8 * 4; i += 256) {
        int wl  = i & 3;
        int r   = (i >> 2) & 7;
        int cil = i >> 5;
        int hp  = (r < 4) ? r : (r + 40);
        inP[(cil * 48 + hp) * 4 + wl] = 0.f;
    }
    // Load ci half 0 (rolled columns).
    {
        const float* sb = src + (size_t)b * CH * HH * WW;
        for (int i = t; i < 64 * 40 * 4; i += 256) {
            int wl  = i & 3;
            int hh  = (i >> 2) % 40;
            int cil = i / 160;
            inP[(cil * 48 + 4 + hh) * 4 + wl] = sb[((size_t)cil * HH + hh) * WW + ws[wl]];
        }
    }
    stage_wchunk<256>(Wb0, w9, 0, t);
    CP_COMMIT();

    unsigned long long acc[8][5];
#pragma unroll
    for (int c = 0; c < 8; ++c)
#pragma unroll
        for (int jj = 0; jj < 5; ++jj) acc[c][jj] = 0ull;

#pragma unroll 1
    for (int q = 0; q < 32; ++q) {         // global ci base = q*4
        CP_WAIT0();
        __syncthreads();
        if (q == 16) {                     // switch inP to ci half 1
            const float* sb = src + ((size_t)b * CH + 64) * HH * WW;
            for (int i = t; i < 64 * 40 * 4; i += 256) {
                int wl  = i & 3;
                int hh  = (i >> 2) % 40;
                int cil = i / 160;
                inP[(cil * 48 + 4 + hh) * 4 + wl] = sb[((size_t)cil * HH + hh) * WW + ws[wl]];
            }
        }
        if (q < 31) {
            stage_wchunk<256>((q & 1) ? Wb0 : Wb1, w9, (q + 1) * 4, t);
            CP_COMMIT();
        }
        if (q == 16) __syncthreads();      // new inP visible before compute
        const float* buf = (q & 1) ? Wb1 : Wb0;

#pragma unroll 1
        for (int cil = 0; cil < 4; ++cil) {
            const float* wrow = buf + cil * WSHB_ROWF + woff;
            const float* irow = inP + ((((q & 15) * 4) + cil) * 48 + h0) * 4 + w_g * 2;
#pragma unroll
            for (int k = 0; k < 9; ++k) {
                float4 wa = *(const float4*)(wrow + k * 4 * WSHB_ROWF);
                float4 wb = *(const float4*)(wrow + k * 4 * WSHB_ROWF + 4);
                unsigned long long ip[5];
#pragma unroll
                for (int jj = 0; jj < 5; ++jj)
                    ip[jj] = *(const unsigned long long*)(irow + (k + jj) * 4);
                unsigned long long s0, s1, s2, s3, s4, s5, s6, s7;
                SPLAT(s0, wa.x); SPLAT(s1, wa.y); SPLAT(s2, wa.z); SPLAT(s3, wa.w);
                SPLAT(s4, wb.x); SPLAT(s5, wb.y); SPLAT(s6, wb.z); SPLAT(s7, wb.w);
#pragma unroll
                for (int jj = 0; jj < 5; ++jj) {
                    FFMA2(acc[0][jj], s0, ip[jj]);
                    FFMA2(acc[1][jj], s1, ip[jj]);
                    FFMA2(acc[2][jj], s2, ip[jj]);
                    FFMA2(acc[3][jj], s3, ip[jj]);
                    FFMA2(acc[4][jj], s4, ip[jj]);
                    FFMA2(acc[5][jj], s5, ip[jj]);
                    FFMA2(acc[6][jj], s6, ip[jj]);
                    FFMA2(acc[7][jj], s7, ip[jj]);
                }
            }
        }
    }

    // Stage 2*relu(conv) into smem [h][co][4w], then float4 global RMW.
    __syncthreads();
    float* so = sm;                    // needs 40*128*4 = 20,480 <= 22,368 floats
#pragma unroll
    for (int c = 0; c < 8; ++c) {
#pragma unroll
        for (int jj = 0; jj < 5; ++jj) {
            unsigned int lo, hi;
            asm("mov.b64 {%0, %1}, %2;" : "=r"(lo), "=r"(hi) : "l"(acc[c][jj]));
            float v0 = 2.0f * fmaxf(__uint_as_float(lo), 0.f);
            float v1 = 2.0f * fmaxf(__uint_as_float(hi), 0.f);
            *(float2*)&so[((h0 + jj) * 128 + co0 + c) * 4 + w_g * 2] = make_float2(v0, v1);
        }
    }
    __syncthreads();
    for (int i = t; i < 40 * 128; i += 256) {
        int hh = i >> 7, co = i & 127;
        float4 sv = *(const float4*)&so[i * 4];
        size_t gi = (((size_t)b * CH + co) * HH + hh) * WW + w0;
        float4 s4 = *(const float4*)(src + gi);
        float4 o4;
        o4.x = s4.x + sv.x; o4.y = s4.y + sv.y; o4.z = s4.z + sv.z; o4.w = s4.w + sv.w;
        *(float4*)(dst + gi) = o4;
    }
}

// ---------------------------------------------------------------------------
// Launcher: weight transpose + 20 chained step kernels, ping-pong buffers.
// Graph-capturable: kernel launches only.
// ---------------------------------------------------------------------------
extern "C" void kernel_launch(void* const* d_in, const int* in_sizes, int n_in,
                              void* d_out, int out_size) {
    const float* x  = (const float*)d_in[0];
    const float* wd = (const float*)d_in[1];
    const float* wu = (const float*)d_in[2];
    const float* wr = (const float*)d_in[3];
    const float* wl = (const float*)d_in[4];
    float* out = (float*)d_out;

    cudaFuncSetAttribute(step_h_kernel, cudaFuncAttributeMaxDynamicSharedMemorySize, SMEM_H);
    cudaFuncSetAttribute(step_v_kernel, cudaFuncAttributeMaxDynamicSharedMemorySize, SMEM_V);

    transpose_w_kernel<<<(WTOT + 255) / 256, 256>>>(wd, wu, wr, wl);

    static const int offH[5] = {1, 2, 5, 10, 20};    // 40 >> (5-i)
    static const int offW[5] = {3, 6, 12, 24, 48};   // 96 >> (5-i)

    int cur_sel = -1;   // step 0 reads external x
    for (int s = 0; s < 20; ++s) {
        int dst_sel = (s == 19) ? -1 : (s & 1);      // final step writes d_out
        int dir = s / 5, it = s % 5;
        int widx = dir * 5 + it;
        if (dir < 2) {
            int shift = (dir == 0) ? offH[it] : HH - offH[it];
            step_h_kernel<<<dim3(HH, BB), 192, SMEM_H>>>(x, out, cur_sel, dst_sel, widx, shift);
        } else {
            int shift = (dir == 2) ? offW[it] : WW - offW[it];
            step_v_kernel<<<dim3(WW / 4, BB), 256, SMEM_V>>>(x, out, cur_sel, dst_sel, widx, shift);
        }
        cur_sel = dst_sel;
    }
}